// round 12
// baseline (speedup 1.0000x reference)
#include <cuda_runtime.h>
#include <cuda_bf16.h>
#include <stdint.h>
#include <math.h>

#define ZB   16
#define ZD   256
#define ZT   4096
#define NVEC (ZB*ZT)            // 65536
#define NELEM (ZB*ZD*ZT)        // 16777216
#define NCODE 1024

#define TILE_M 64
#define TILE_N 128
#define BK     32
#define NT_TILES (NCODE/TILE_N)   // 8
#define KCH      (ZD/BK)          // 8
#define NITER    (NT_TILES*KCH)   // 64
#define THREADS  256

// A (hi only): row stride 264 bf16 = 528 B
#define STRA_B 528
#define A_H_OFF 0
#define B_BASE (TILE_M*STRA_B)             // 33792
// B chunk: 128 rows x 80B, hi+lo, double buffered
#define STRB_B 80
#define B_HL   (TILE_N*STRB_B)             // 10240
#define B_BUF  (2*B_HL)                    // 20480
#define SMEM_TOTAL (B_BASE + 2*B_BUF)      // 74752
// epilogue scratch overlaps B region (B dead by then)
#define STD    B_BASE                      // [row][wn][3] float
#define STI    (B_BASE + TILE_M*4*3*4)     // +3072

// ---------------- scratch --------------------------------------------------
__device__ __align__(16) __nv_bfloat16 g_eh[NCODE*ZD];
__device__ __align__(16) __nv_bfloat16 g_el[NCODE*ZD];
__device__ int           g_idx[NVEC];
__device__ unsigned int  g_hist[NCODE];
__device__ float         g_enorm[NCODE];
__device__ float         g_Me;            // max ||e||
__device__ float4        g_top[NVEC];     // d1,d2,d3,margin(=2*eps)
__device__ int4          g_topi[NVEC];
__device__ double        g_loss;

// ---------------- helpers --------------------------------------------------
__device__ __forceinline__ void mma_bf16(float c[4], uint32_t a0, uint32_t a1,
                                         uint32_t a2, uint32_t a3,
                                         uint32_t b0, uint32_t b1) {
    asm volatile(
        "mma.sync.aligned.m16n8k16.row.col.f32.bf16.bf16.f32 "
        "{%0,%1,%2,%3}, {%4,%5,%6,%7}, {%8,%9}, {%0,%1,%2,%3};"
        : "+f"(c[0]), "+f"(c[1]), "+f"(c[2]), "+f"(c[3])
        : "r"(a0), "r"(a1), "r"(a2), "r"(a3), "r"(b0), "r"(b1));
}
#define CP_ASYNC16(dst, src) \
    asm volatile("cp.async.cg.shared.global [%0], [%1], 16;" :: "r"(dst), "l"(src))
#define CP_COMMIT() asm volatile("cp.async.commit_group;" ::: "memory")
#define CP_WAIT1()  asm volatile("cp.async.wait_group 1;" ::: "memory")

__device__ __forceinline__ uint32_t smem_u32(const void* p) {
    uint32_t a;
    asm("{ .reg .u64 t; cvta.to.shared.u64 t, %1; cvt.u32.u64 %0, t; }" : "=r"(a) : "l"(p));
    return a;
}
__device__ __forceinline__ void ins3(float d, int c,
        float& d1, int& i1, float& d2, int& i2, float& d3, int& i3) {
    if (d < d3) {
        if (d < d2) {
            d3 = d2; i3 = i2;
            if (d < d1) { d2 = d1; i2 = i1; d1 = d; i1 = c; }
            else        { d2 = d;  i2 = c; }
        } else { d3 = d; i3 = c; }
    }
}

// ---------------- kernel 1: init + codebook prep ---------------------------
__global__ __launch_bounds__(256) void vq_embprep(const float* __restrict__ emb) {
    int c = blockIdx.x, d = threadIdx.x;
    if (d == 0) {
        g_hist[c] = 0u;
        if (c == 0) g_loss = 0.0;
    }
    float v = emb[(size_t)c * ZD + d];
    __nv_bfloat16 h = __float2bfloat16_rn(v);
    float hf = __bfloat162float(h);
    g_eh[(size_t)c * ZD + d] = h;
    g_el[(size_t)c * ZD + d] = __float2bfloat16_rn(v - hf);

    float sv = v * v;
    __shared__ float wv[8];
    int lane = d & 31, w = d >> 5;
    #pragma unroll
    for (int o = 16; o > 0; o >>= 1) sv += __shfl_down_sync(0xffffffffu, sv, o);
    if (lane == 0) wv[w] = sv;
    __syncthreads();
    if (d == 0) {
        float tv = 0.f;
        #pragma unroll
        for (int i = 0; i < 8; i++) tv += wv[i];
        g_enorm[c] = tv;
    }
}

// ---------------- kernel 2: max ||e|| --------------------------------------
__global__ void vq_maxred() {
    __shared__ float mh[32];
    int t = threadIdx.x, lane = t & 31, w = t >> 5;
    float a = g_enorm[t];
    #pragma unroll
    for (int o = 16; o > 0; o >>= 1) a = fmaxf(a, __shfl_down_sync(0xffffffffu, a, o));
    if (lane == 0) mh[w] = a;
    __syncthreads();
    if (w == 0) {
        float x = mh[lane];
        #pragma unroll
        for (int o = 16; o > 0; o >>= 1) x = fmaxf(x, __shfl_down_sync(0xffffffffu, x, o));
        if (lane == 0) g_Me = sqrtf(x) * 1.001f;
    }
}

// ---------------- kernel 3: 2-pass HMMA approx top-3 (unchanged, passing) --
extern __shared__ char smem[];

__device__ __forceinline__ void prefetch_chunk(int it2, int tid) {
    int nt = it2 >> 3, kc = it2 & 7, buf = it2 & 1;
    #pragma unroll
    for (int q = 0; q < 4; q++) {
        int idx = tid + q * THREADS;        // 0..1023
        int hl  = idx >> 9;
        int rem = idx & 511;
        int row = rem >> 2;
        int seg = rem & 3;
        const __nv_bfloat16* src =
            (hl ? g_el : g_eh) + ((size_t)(nt * TILE_N + row) * ZD + kc * BK + seg * 8);
        uint32_t dst = smem_u32(smem) + B_BASE + buf * B_BUF + hl * B_HL
                     + row * STRB_B + seg * 16;
        CP_ASYNC16(dst, src);
    }
}

__global__ __launch_bounds__(THREADS, 2)
void vq_argmin_p2(const float* __restrict__ z) {
    __shared__ float sZl2[TILE_M];
    int tid = threadIdx.x, lane = tid & 31, wid = tid >> 5;
    int g = lane >> 2, t4 = lane & 3;
    int wm = wid & 1, wn = wid >> 1;

    int n0 = blockIdx.x * TILE_M;
    int b  = n0 / ZT, t0 = n0 % ZT;
    const float* zb = z + (size_t)b * ZD * ZT + t0;

    if (tid < TILE_M) sZl2[tid] = 0.f;
    __syncthreads();

    // A tile (hi) + per-row ||zl||^2  (64 rows x 256 dims)
    {
        int r = tid & 63;
        float l2p = 0.f;
        #pragma unroll 1
        for (int itl = 0; itl < 8; itl++) {
            int kq = (tid >> 6) + itl * 4;       // 0..31
            union { __nv_bfloat16 h[8]; uint4 u; } H;
            #pragma unroll
            for (int j = 0; j < 8; j++) {
                float v = zb[(size_t)(kq * 8 + j) * ZT + r];
                __nv_bfloat16 hh = __float2bfloat16_rn(v);
                float lf = __bfloat162float(__float2bfloat16_rn(v - __bfloat162float(hh)));
                H.h[j] = hh;
                l2p = fmaf(lf, lf, l2p);
            }
            *(uint4*)(smem + A_H_OFF + (uint32_t)(r * STRA_B + kq * 16)) = H.u;
        }
        atomicAdd(&sZl2[r], l2p);
    }

    prefetch_chunk(0, tid);
    CP_COMMIT();
    __syncthreads();

    float c[2][4][4];
    #pragma unroll
    for (int i = 0; i < 2; i++)
        #pragma unroll
        for (int j = 0; j < 4; j++)
            #pragma unroll
            for (int r = 0; r < 4; r++) c[i][j][r] = 0.f;

    float td[2][2][3];
    int   ti[2][2][3];
    #pragma unroll
    for (int i = 0; i < 2; i++)
        #pragma unroll
        for (int h = 0; h < 2; h++)
            #pragma unroll
            for (int k = 0; k < 3; k++) { td[i][h][k] = 3.4e38f; ti[i][h][k] = 0; }

    #pragma unroll 1
    for (int it = 0; it < NITER; it++) {
        int nt = it >> 3, kc = it & 7;
        int buf = it & 1;
        if (it + 1 < NITER) prefetch_chunk(it + 1, tid);
        CP_COMMIT();
        CP_WAIT1();
        __syncthreads();

        const char* Bh = smem + B_BASE + buf * B_BUF;
        const char* Bl = Bh + B_HL;

        #pragma unroll
        for (int ks = 0; ks < 2; ks++) {
            uint32_t kb = (uint32_t)(kc * BK + ks * 16);
            uint32_t ah[2][4], bh[4][2], bl[4][2];
            #pragma unroll
            for (int i = 0; i < 2; i++) {
                int m0 = wm * 32 + i * 16 + g;
                const char* base = smem + A_H_OFF + m0 * STRA_B + (kb + 2 * t4) * 2;
                ah[i][0] = *(const uint32_t*)(base);
                ah[i][1] = *(const uint32_t*)(base + 8 * STRA_B);
                ah[i][2] = *(const uint32_t*)(base + 16);
                ah[i][3] = *(const uint32_t*)(base + 8 * STRA_B + 16);
            }
            #pragma unroll
            for (int j = 0; j < 4; j++) {
                int row = wn * 32 + j * 8 + g;
                const char* base = Bh + row * STRB_B + (ks * 16 + 2 * t4) * 2;
                bh[j][0] = *(const uint32_t*)(base);
                bh[j][1] = *(const uint32_t*)(base + 16);
            }
            #pragma unroll
            for (int i = 0; i < 2; i++)
                #pragma unroll
                for (int j = 0; j < 4; j++)
                    mma_bf16(c[i][j], ah[i][0], ah[i][1], ah[i][2], ah[i][3],
                             bh[j][0], bh[j][1]);
            #pragma unroll
            for (int j = 0; j < 4; j++) {
                int row = wn * 32 + j * 8 + g;
                const char* base = Bl + row * STRB_B + (ks * 16 + 2 * t4) * 2;
                bl[j][0] = *(const uint32_t*)(base);
                bl[j][1] = *(const uint32_t*)(base + 16);
            }
            #pragma unroll
            for (int i = 0; i < 2; i++)
                #pragma unroll
                for (int j = 0; j < 4; j++)
                    mma_bf16(c[i][j], ah[i][0], ah[i][1], ah[i][2], ah[i][3],
                             bl[j][0], bl[j][1]);
        }

        if (kc == KCH - 1) {
            #pragma unroll
            for (int j = 0; j < 4; j++) {
                int col0 = nt * TILE_N + wn * 32 + j * 8 + 2 * t4;
                float e0 = __ldg(&g_enorm[col0]);
                float e1 = __ldg(&g_enorm[col0 + 1]);
                #pragma unroll
                for (int i = 0; i < 2; i++) {
                    ins3(fmaf(-2.f, c[i][j][0], e0), col0,
                         td[i][0][0], ti[i][0][0], td[i][0][1], ti[i][0][1], td[i][0][2], ti[i][0][2]);
                    ins3(fmaf(-2.f, c[i][j][1], e1), col0 + 1,
                         td[i][0][0], ti[i][0][0], td[i][0][1], ti[i][0][1], td[i][0][2], ti[i][0][2]);
                    ins3(fmaf(-2.f, c[i][j][2], e0), col0,
                         td[i][1][0], ti[i][1][0], td[i][1][1], ti[i][1][1], td[i][1][2], ti[i][1][2]);
                    ins3(fmaf(-2.f, c[i][j][3], e1), col0 + 1,
                         td[i][1][0], ti[i][1][0], td[i][1][1], ti[i][1][1], td[i][1][2], ti[i][1][2]);
                    c[i][j][0] = c[i][j][1] = c[i][j][2] = c[i][j][3] = 0.f;
                }
            }
        }
        __syncthreads();
    }

    // quad (t4) merge
    #pragma unroll
    for (int i = 0; i < 2; i++)
        #pragma unroll
        for (int h = 0; h < 2; h++)
            #pragma unroll
            for (int sh = 1; sh <= 2; sh <<= 1)
                #pragma unroll
                for (int k = 0; k < 3; k++) {
                    float od = __shfl_xor_sync(0xffffffffu, td[i][h][k], sh);
                    int   oc = __shfl_xor_sync(0xffffffffu, ti[i][h][k], sh);
                    ins3(od, oc, td[i][h][0], ti[i][h][0], td[i][h][1], ti[i][h][1],
                         td[i][h][2], ti[i][h][2]);
                }

    float* stD = (float*)(smem + STD);
    int*   stI = (int*)(smem + STI);
    if (t4 == 0) {
        #pragma unroll
        for (int i = 0; i < 2; i++)
            #pragma unroll
            for (int h = 0; h < 2; h++) {
                int row = wm * 32 + i * 16 + h * 8 + g;   // 0..63
                #pragma unroll
                for (int k = 0; k < 3; k++) {
                    stD[(row * 4 + wn) * 3 + k] = td[i][h][k];
                    stI[(row * 4 + wn) * 3 + k] = ti[i][h][k];
                }
            }
    }
    __syncthreads();
    if (tid < TILE_M) {
        float d1 = 3.4e38f, d2 = 3.4e38f, d3 = 3.4e38f;
        int   i1 = 0, i2 = 0, i3 = 0;
        #pragma unroll
        for (int w = 0; w < 4; w++)
            #pragma unroll
            for (int k = 0; k < 3; k++)
                ins3(stD[(tid * 4 + w) * 3 + k], stI[(tid * 4 + w) * 3 + k],
                     d1, i1, d2, i2, d3, i3);
        float zl = sqrtf(sZl2[tid]);
        // one-sided error eps = 2*||zl||*Me (+pad); store margin = 2*eps
        float margin = 4.3f * zl * g_Me + 0.25f;
        g_top[n0 + tid]  = make_float4(d1, d2, d3, margin);
        g_topi[n0 + tid] = make_int4(i1, i2, i3, 0);
    }
}

// ---------------- kernel 4: exact resolve (rebuilt) ------------------------
__global__ __launch_bounds__(256)
void vq_resolve(const float* __restrict__ z, const float* __restrict__ emb) {
    __shared__ float zs[8][256];
    int lane = threadIdx.x & 31, wid = threadIdx.x >> 5;
    int row = blockIdx.x * 8 + wid;

    float4 t = g_top[row];
    int4   ix = g_topi[row];
    int idx;
    if (t.y - t.x > t.w) {
        idx = ix.x;                            // fast path: no memory touched
    } else {
        float eps = 0.5f * t.w;
        int b = row / ZT, tt = row % ZT;
        const float* zp = z + (size_t)b * ZD * ZT + tt;
        float zr[8];
        #pragma unroll
        for (int j = 0; j < 8; j++) zr[j] = zp[(size_t)(lane * 8 + j) * ZT];

        // exact fp32 distance (sans ||z||^2) via warp dot
        auto edist = [&](int cc) -> float {
            const float4* e4 = (const float4*)(emb + (size_t)cc * ZD + lane * 8);
            float4 ea = e4[0], eb = e4[1];
            float s = zr[0] * ea.x + zr[1] * ea.y + zr[2] * ea.z + zr[3] * ea.w
                    + zr[4] * eb.x + zr[5] * eb.y + zr[6] * eb.z + zr[7] * eb.w;
            #pragma unroll
            for (int o = 16; o > 0; o >>= 1) s += __shfl_xor_sync(0xffffffffu, s, o);
            return fmaf(-2.f, s, __ldg(&g_enorm[cc]));
        };

        // exact distances for the approx top-3; lexicographic (d, idx) min
        float bd = edist(ix.x); int bi = ix.x;
        {
            float d2 = edist(ix.y);
            if (d2 < bd || (d2 == bd && ix.y < bi)) { bd = d2; bi = ix.y; }
            float d3 = edist(ix.z);
            if (d3 < bd || (d3 == bd && ix.z < bi)) { bd = d3; bi = ix.z; }
        }
        // any code outside top-3 has true d >= approx_d3 - eps
        if (bd < t.z - eps) {
            idx = bi;
        } else {
            // full exact scan, shfl-free: z row staged in smem (broadcast),
            // each lane owns 32 consecutive codes, sequential e reads.
            #pragma unroll
            for (int j = 0; j < 8; j++) zs[wid][lane * 8 + j] = zr[j];
            __syncwarp();
            float fbd = 3.4e38f; int fbi = 0;
            #pragma unroll 1
            for (int ci = 0; ci < 32; ci++) {
                int cc = lane * 32 + ci;
                const float4* er = (const float4*)(emb + (size_t)cc * ZD);
                float s0 = 0.f, s1 = 0.f;
                #pragma unroll
                for (int d4 = 0; d4 < 32; d4++) {
                    float4 e0 = er[2 * d4], e1 = er[2 * d4 + 1];
                    const float* zq = &zs[wid][d4 * 8];
                    s0 += zq[0] * e0.x + zq[1] * e0.y + zq[2] * e0.z + zq[3] * e0.w;
                    s1 += zq[4] * e1.x + zq[5] * e1.y + zq[6] * e1.z + zq[7] * e1.w;
                }
                float dist = fmaf(-2.f, s0 + s1, __ldg(&g_enorm[cc]));
                if (dist < fbd) { fbd = dist; fbi = cc; }   // ci ascending => first-min
            }
            // warp reduce lexicographic (d, c)
            #pragma unroll
            for (int o = 16; o > 0; o >>= 1) {
                float od = __shfl_xor_sync(0xffffffffu, fbd, o);
                int   oc = __shfl_xor_sync(0xffffffffu, fbi, o);
                if (od < fbd || (od == fbd && oc < fbi)) { fbd = od; fbi = oc; }
            }
            idx = fbi;
        }
    }
    if (lane == 0) {
        g_idx[row] = idx;
        atomicAdd(&g_hist[idx], 1u);
    }
}

// ---------------- kernel 5: coalesced gather + output + loss ---------------
__global__ __launch_bounds__(256)
void vq_gather_kernel(const float* __restrict__ z, const float* __restrict__ emb,
                      float* __restrict__ out) {
    __shared__ int   sidx[32];
    __shared__ float sE[32][257];
    int tid = threadIdx.x;
    int b   = blockIdx.x >> 7;
    int t0  = (blockIdx.x & 127) * 32;

    if (tid < 32) sidx[tid] = g_idx[b * ZT + t0 + tid];
    __syncthreads();

    {
        int r = tid >> 3;
        const float* row = emb + (size_t)sidx[r] * ZD;
        #pragma unroll
        for (int q = 0; q < 8; q++) {
            int c4 = (tid & 7) + q * 8;
            float4 v = *(const float4*)(row + c4 * 4);
            sE[r][c4 * 4 + 0] = v.x;
            sE[r][c4 * 4 + 1] = v.y;
            sE[r][c4 * 4 + 2] = v.z;
            sE[r][c4 * 4 + 3] = v.w;
        }
    }
    __syncthreads();

    float lsum = 0.f;
    int w = tid >> 5, lane = tid & 31;
    #pragma unroll 4
    for (int d = w; d < ZD; d += 8) {
        float e = sE[lane][d];
        size_t off = ((size_t)(b * ZD + d)) * ZT + t0 + lane;
        float zv = z[off];
        out[off] = e;
        float df = zv - e;
        lsum = fmaf(df, df, lsum);
    }

    __shared__ float ws[8];
    #pragma unroll
    for (int o = 16; o > 0; o >>= 1) lsum += __shfl_down_sync(0xffffffffu, lsum, o);
    if (lane == 0) ws[w] = lsum;
    __syncthreads();
    if (w == 0) {
        float s = (lane < 8) ? ws[lane] : 0.f;
        #pragma unroll
        for (int o = 4; o > 0; o >>= 1) s += __shfl_down_sync(0xffffffffu, s, o);
        if (lane == 0) atomicAdd(&g_loss, (double)s);
    }
}

// ---------------- kernel 6: perplexity + scalar outputs --------------------
__global__ void vq_finalize_kernel(float* __restrict__ out, int out_size) {
    __shared__ float warpsum[32];
    int t = threadIdx.x;
    float p = (float)g_hist[t] / (float)NVEC;
    float term = p * logf(p + 1e-10f);
    int lane = t & 31, w = t >> 5;
    #pragma unroll
    for (int o = 16; o > 0; o >>= 1) term += __shfl_down_sync(0xffffffffu, term, o);
    if (lane == 0) warpsum[w] = term;
    __syncthreads();
    if (w == 0) {
        float s = warpsum[lane];
        #pragma unroll
        for (int o = 16; o > 0; o >>= 1) s += __shfl_down_sync(0xffffffffu, s, o);
        if (lane == 0) {
            float perp = expf(-s);
            float loss = (float)g_loss;
            out[out_size - 3] = loss;
            out[out_size - 2] = loss;
            out[out_size - 1] = perp;
        }
    }
}

// ---------------- launcher -------------------------------------------------
extern "C" void kernel_launch(void* const* d_in, const int* in_sizes, int n_in,
                              void* d_out, int out_size) {
    const float* z   = (const float*)d_in[0];
    const float* emb = (const float*)d_in[1];
    if (n_in >= 2 && in_sizes[0] == NCODE * ZD && in_sizes[1] == NELEM) {
        const float* tmp = z; z = emb; emb = tmp;
    }
    float* out = (float*)d_out;

    cudaFuncSetAttribute(vq_argmin_p2,
                         cudaFuncAttributeMaxDynamicSharedMemorySize, SMEM_TOTAL);

    vq_embprep<<<NCODE, 256>>>(emb);
    vq_maxred<<<1, 1024>>>();
    vq_argmin_p2<<<NVEC / TILE_M, THREADS, SMEM_TOTAL>>>(z);
    vq_resolve<<<NVEC / 8, 256>>>(z, emb);
    vq_gather_kernel<<<ZB * (ZT / 32), 256>>>(z, emb, out);
    vq_finalize_kernel<<<1, 1024>>>(out, out_size);
}

// round 13
// speedup vs baseline: 2.8240x; 2.8240x over previous
#include <cuda_runtime.h>
#include <cuda_bf16.h>
#include <stdint.h>
#include <math.h>

#define ZB   16
#define ZD   256
#define ZT   4096
#define NVEC (ZB*ZT)            // 65536
#define NELEM (ZB*ZD*ZT)        // 16777216
#define NCODE 1024

#define TILE_M 64
#define TILE_N 128
#define BK     32
#define NT_TILES (NCODE/TILE_N)   // 8
#define KCH      (ZD/BK)          // 8
#define NITER    (NT_TILES*KCH)   // 64
#define THREADS  256

// A hi+lo: row stride 264 bf16 = 528 B
#define STRA_B 528
#define A_H_OFF 0
#define A_L_OFF (TILE_M*STRA_B)            // 33792
#define B_BASE (2*TILE_M*STRA_B)           // 67584
// B chunk: 128 rows x 80B, hi+lo, double buffered
#define STRB_B 80
#define B_HL   (TILE_N*STRB_B)             // 10240
#define B_BUF  (2*B_HL)                    // 20480
#define SMEM_TOTAL (B_BASE + 2*B_BUF)      // 108544
// epilogue scratch overlaps B region (B dead by then)
#define STD    B_BASE                      // [row][wn] float
#define STI    (B_BASE + TILE_M*4*4)       // +1024

// ---------------- scratch --------------------------------------------------
__device__ __align__(16) __nv_bfloat16 g_eh[NCODE*ZD];
__device__ __align__(16) __nv_bfloat16 g_el[NCODE*ZD];
__device__ int           g_idx[NVEC];
__device__ unsigned int  g_hist[NCODE];
__device__ float         g_enorm[NCODE];
__device__ double        g_loss;

// ---------------- helpers --------------------------------------------------
__device__ __forceinline__ void mma_bf16(float c[4], uint32_t a0, uint32_t a1,
                                         uint32_t a2, uint32_t a3,
                                         uint32_t b0, uint32_t b1) {
    asm volatile(
        "mma.sync.aligned.m16n8k16.row.col.f32.bf16.bf16.f32 "
        "{%0,%1,%2,%3}, {%4,%5,%6,%7}, {%8,%9}, {%0,%1,%2,%3};"
        : "+f"(c[0]), "+f"(c[1]), "+f"(c[2]), "+f"(c[3])
        : "r"(a0), "r"(a1), "r"(a2), "r"(a3), "r"(b0), "r"(b1));
}
#define CP_ASYNC16(dst, src) \
    asm volatile("cp.async.cg.shared.global [%0], [%1], 16;" :: "r"(dst), "l"(src))
#define CP_COMMIT() asm volatile("cp.async.commit_group;" ::: "memory")
#define CP_WAIT1()  asm volatile("cp.async.wait_group 1;" ::: "memory")

__device__ __forceinline__ uint32_t smem_u32(const void* p) {
    uint32_t a;
    asm("{ .reg .u64 t; cvta.to.shared.u64 t, %1; cvt.u32.u64 %0, t; }" : "=r"(a) : "l"(p));
    return a;
}

// ---------------- kernel 1: init + codebook prep ---------------------------
__global__ __launch_bounds__(256) void vq_embprep(const float* __restrict__ emb) {
    int c = blockIdx.x, d = threadIdx.x;
    if (d == 0) {
        g_hist[c] = 0u;
        if (c == 0) g_loss = 0.0;
    }
    float v = emb[(size_t)c * ZD + d];
    __nv_bfloat16 h = __float2bfloat16_rn(v);
    float hf = __bfloat162float(h);
    g_eh[(size_t)c * ZD + d] = h;
    g_el[(size_t)c * ZD + d] = __float2bfloat16_rn(v - hf);

    float sv = v * v;
    __shared__ float wv[8];
    int lane = d & 31, w = d >> 5;
    #pragma unroll
    for (int o = 16; o > 0; o >>= 1) sv += __shfl_down_sync(0xffffffffu, sv, o);
    if (lane == 0) wv[w] = sv;
    __syncthreads();
    if (d == 0) {
        float tv = 0.f;
        #pragma unroll
        for (int i = 0; i < 8; i++) tv += wv[i];
        g_enorm[c] = tv;
    }
}

// ---------------- kernel 2: 3-pass HMMA exact argmin -----------------------
extern __shared__ char smem[];

__device__ __forceinline__ void prefetch_chunk(int it2, int tid) {
    int nt = it2 >> 3, kc = it2 & 7, buf = it2 & 1;
    #pragma unroll
    for (int q = 0; q < 4; q++) {
        int idx = tid + q * THREADS;        // 0..1023
        int hl  = idx >> 9;
        int rem = idx & 511;
        int row = rem >> 2;
        int seg = rem & 3;
        const __nv_bfloat16* src =
            (hl ? g_el : g_eh) + ((size_t)(nt * TILE_N + row) * ZD + kc * BK + seg * 8);
        uint32_t dst = smem_u32(smem) + B_BASE + buf * B_BUF + hl * B_HL
                     + row * STRB_B + seg * 16;
        CP_ASYNC16(dst, src);
    }
}

__global__ __launch_bounds__(THREADS, 2)
void vq_argmin_3p(const float* __restrict__ z) {
    int tid = threadIdx.x, lane = tid & 31, wid = tid >> 5;
    int g = lane >> 2, t4 = lane & 3;
    int wm = wid & 1, wn = wid >> 1;

    int n0 = blockIdx.x * TILE_M;
    int b  = n0 / ZT, t0 = n0 % ZT;
    const float* zb = z + (size_t)b * ZD * ZT + t0;

    // A tile: hi + lo split (64 rows x 256 dims)
    {
        int r = tid & 63;
        #pragma unroll 1
        for (int itl = 0; itl < 8; itl++) {
            int kq = (tid >> 6) + itl * 4;       // 0..31
            union { __nv_bfloat16 h[8]; uint4 u; } H, L;
            #pragma unroll
            for (int j = 0; j < 8; j++) {
                float v = zb[(size_t)(kq * 8 + j) * ZT + r];
                __nv_bfloat16 hh = __float2bfloat16_rn(v);
                H.h[j] = hh;
                L.h[j] = __float2bfloat16_rn(v - __bfloat162float(hh));
            }
            uint32_t off = (uint32_t)(r * STRA_B + kq * 16);
            *(uint4*)(smem + A_H_OFF + off) = H.u;
            *(uint4*)(smem + A_L_OFF + off) = L.u;
        }
    }

    prefetch_chunk(0, tid);
    CP_COMMIT();
    __syncthreads();

    float c[2][4][4];
    #pragma unroll
    for (int i = 0; i < 2; i++)
        #pragma unroll
        for (int j = 0; j < 4; j++)
            #pragma unroll
            for (int r = 0; r < 4; r++) c[i][j][r] = 0.f;

    float bd[2][2];
    int   bc[2][2];
    #pragma unroll
    for (int i = 0; i < 2; i++) { bd[i][0] = bd[i][1] = 3.4e38f; bc[i][0] = bc[i][1] = 0; }

    #pragma unroll 1
    for (int it = 0; it < NITER; it++) {
        int nt = it >> 3, kc = it & 7;
        int buf = it & 1;
        if (it + 1 < NITER) prefetch_chunk(it + 1, tid);
        CP_COMMIT();
        CP_WAIT1();
        __syncthreads();

        const char* Bh = smem + B_BASE + buf * B_BUF;
        const char* Bl = Bh + B_HL;

        #pragma unroll
        for (int ks = 0; ks < 2; ks++) {
            uint32_t kb = (uint32_t)(kc * BK + ks * 16);
            uint32_t ah[2][4], al[2][4], bh[4][2], bl[4][2];
            #pragma unroll
            for (int i = 0; i < 2; i++) {
                int m0 = wm * 32 + i * 16 + g;
                const char* baseH = smem + A_H_OFF + m0 * STRA_B + (kb + 2 * t4) * 2;
                ah[i][0] = *(const uint32_t*)(baseH);
                ah[i][1] = *(const uint32_t*)(baseH + 8 * STRA_B);
                ah[i][2] = *(const uint32_t*)(baseH + 16);
                ah[i][3] = *(const uint32_t*)(baseH + 8 * STRA_B + 16);
            }
            #pragma unroll
            for (int j = 0; j < 4; j++) {
                int row = wn * 32 + j * 8 + g;
                const char* base = Bh + row * STRB_B + (ks * 16 + 2 * t4) * 2;
                bh[j][0] = *(const uint32_t*)(base);
                bh[j][1] = *(const uint32_t*)(base + 16);
            }
            // pass 1: Ah * Bh
            #pragma unroll
            for (int i = 0; i < 2; i++)
                #pragma unroll
                for (int j = 0; j < 4; j++)
                    mma_bf16(c[i][j], ah[i][0], ah[i][1], ah[i][2], ah[i][3],
                             bh[j][0], bh[j][1]);
            // pass 2: Ah * Bl
            #pragma unroll
            for (int j = 0; j < 4; j++) {
                int row = wn * 32 + j * 8 + g;
                const char* base = Bl + row * STRB_B + (ks * 16 + 2 * t4) * 2;
                bl[j][0] = *(const uint32_t*)(base);
                bl[j][1] = *(const uint32_t*)(base + 16);
            }
            #pragma unroll
            for (int i = 0; i < 2; i++)
                #pragma unroll
                for (int j = 0; j < 4; j++)
                    mma_bf16(c[i][j], ah[i][0], ah[i][1], ah[i][2], ah[i][3],
                             bl[j][0], bl[j][1]);
            // pass 3: Al * Bh
            #pragma unroll
            for (int i = 0; i < 2; i++) {
                int m0 = wm * 32 + i * 16 + g;
                const char* baseL = smem + A_L_OFF + m0 * STRA_B + (kb + 2 * t4) * 2;
                al[i][0] = *(const uint32_t*)(baseL);
                al[i][1] = *(const uint32_t*)(baseL + 8 * STRA_B);
                al[i][2] = *(const uint32_t*)(baseL + 16);
                al[i][3] = *(const uint32_t*)(baseL + 8 * STRA_B + 16);
            }
            #pragma unroll
            for (int i = 0; i < 2; i++)
                #pragma unroll
                for (int j = 0; j < 4; j++)
                    mma_bf16(c[i][j], al[i][0], al[i][1], al[i][2], al[i][3],
                             bh[j][0], bh[j][1]);
        }

        if (kc == KCH - 1) {
            // fold tile nt into running per-row argmin; reset accumulators
            #pragma unroll
            for (int j = 0; j < 4; j++) {
                int col0 = nt * TILE_N + wn * 32 + j * 8 + 2 * t4;
                float e0 = __ldg(&g_enorm[col0]);
                float e1 = __ldg(&g_enorm[col0 + 1]);
                #pragma unroll
                for (int i = 0; i < 2; i++) {
                    float d0 = fmaf(-2.f, c[i][j][0], e0);
                    float d1 = fmaf(-2.f, c[i][j][1], e1);
                    float d2 = fmaf(-2.f, c[i][j][2], e0);
                    float d3 = fmaf(-2.f, c[i][j][3], e1);
                    if (d0 < bd[i][0] || (d0 == bd[i][0] && col0     < bc[i][0])) { bd[i][0] = d0; bc[i][0] = col0;     }
                    if (d1 < bd[i][0] || (d1 == bd[i][0] && col0 + 1 < bc[i][0])) { bd[i][0] = d1; bc[i][0] = col0 + 1; }
                    if (d2 < bd[i][1] || (d2 == bd[i][1] && col0     < bc[i][1])) { bd[i][1] = d2; bc[i][1] = col0;     }
                    if (d3 < bd[i][1] || (d3 == bd[i][1] && col0 + 1 < bc[i][1])) { bd[i][1] = d3; bc[i][1] = col0 + 1; }
                    c[i][j][0] = c[i][j][1] = c[i][j][2] = c[i][j][3] = 0.f;
                }
            }
        }
        __syncthreads();
    }

    // quad (t4) merge, lexicographic (d, c)
    #pragma unroll
    for (int i = 0; i < 2; i++)
        #pragma unroll
        for (int h = 0; h < 2; h++)
            #pragma unroll
            for (int sh = 1; sh <= 2; sh <<= 1) {
                float od = __shfl_xor_sync(0xffffffffu, bd[i][h], sh);
                int   oc = __shfl_xor_sync(0xffffffffu, bc[i][h], sh);
                if (od < bd[i][h] || (od == bd[i][h] && oc < bc[i][h])) {
                    bd[i][h] = od; bc[i][h] = oc;
                }
            }

    float* stD = (float*)(smem + STD);
    int*   stI = (int*)(smem + STI);
    if (t4 == 0) {
        #pragma unroll
        for (int i = 0; i < 2; i++)
            #pragma unroll
            for (int h = 0; h < 2; h++) {
                int row = wm * 32 + i * 16 + h * 8 + g;   // 0..63
                stD[row * 4 + wn] = bd[i][h];
                stI[row * 4 + wn] = bc[i][h];
            }
    }
    __syncthreads();
    if (tid < TILE_M) {
        float fb = stD[tid * 4];
        int   fc = stI[tid * 4];
        #pragma unroll
        for (int w = 1; w < 4; w++) {
            float d  = stD[tid * 4 + w];
            int   cc = stI[tid * 4 + w];
            if (d < fb || (d == fb && cc < fc)) { fb = d; fc = cc; }
        }
        g_idx[n0 + tid] = fc;
        atomicAdd(&g_hist[fc], 1u);
    }
}

// ---------------- kernel 3: coalesced gather + output + loss ---------------
__global__ __launch_bounds__(256)
void vq_gather_kernel(const float* __restrict__ z, const float* __restrict__ emb,
                      float* __restrict__ out) {
    __shared__ int   sidx[32];
    __shared__ float sE[32][257];
    int tid = threadIdx.x;
    int b   = blockIdx.x >> 7;
    int t0  = (blockIdx.x & 127) * 32;

    if (tid < 32) sidx[tid] = g_idx[b * ZT + t0 + tid];
    __syncthreads();

    {
        int r = tid >> 3;
        const float* row = emb + (size_t)sidx[r] * ZD;
        #pragma unroll
        for (int q = 0; q < 8; q++) {
            int c4 = (tid & 7) + q * 8;
            float4 v = *(const float4*)(row + c4 * 4);
            sE[r][c4 * 4 + 0] = v.x;
            sE[r][c4 * 4 + 1] = v.y;
            sE[r][c4 * 4 + 2] = v.z;
            sE[r][c4 * 4 + 3] = v.w;
        }
    }
    __syncthreads();

    float lsum = 0.f;
    int w = tid >> 5, lane = tid & 31;
    #pragma unroll 4
    for (int d = w; d < ZD; d += 8) {
        float e = sE[lane][d];
        size_t off = ((size_t)(b * ZD + d)) * ZT + t0 + lane;
        float zv = z[off];
        out[off] = e;
        float df = zv - e;
        lsum = fmaf(df, df, lsum);
    }

    __shared__ float ws[8];
    #pragma unroll
    for (int o = 16; o > 0; o >>= 1) lsum += __shfl_down_sync(0xffffffffu, lsum, o);
    if (lane == 0) ws[w] = lsum;
    __syncthreads();
    if (w == 0) {
        float s = (lane < 8) ? ws[lane] : 0.f;
        #pragma unroll
        for (int o = 4; o > 0; o >>= 1) s += __shfl_down_sync(0xffffffffu, s, o);
        if (lane == 0) atomicAdd(&g_loss, (double)s);
    }
}

// ---------------- kernel 4: perplexity + scalar outputs --------------------
__global__ void vq_finalize_kernel(float* __restrict__ out, int out_size) {
    __shared__ float warpsum[32];
    int t = threadIdx.x;
    float p = (float)g_hist[t] / (float)NVEC;
    float term = p * logf(p + 1e-10f);
    int lane = t & 31, w = t >> 5;
    #pragma unroll
    for (int o = 16; o > 0; o >>= 1) term += __shfl_down_sync(0xffffffffu, term, o);
    if (lane == 0) warpsum[w] = term;
    __syncthreads();
    if (w == 0) {
        float s = warpsum[lane];
        #pragma unroll
        for (int o = 16; o > 0; o >>= 1) s += __shfl_down_sync(0xffffffffu, s, o);
        if (lane == 0) {
            float perp = expf(-s);
            float loss = (float)g_loss;
            out[out_size - 3] = loss;
            out[out_size - 2] = loss;
            out[out_size - 1] = perp;
        }
    }
}

// ---------------- launcher -------------------------------------------------
extern "C" void kernel_launch(void* const* d_in, const int* in_sizes, int n_in,
                              void* d_out, int out_size) {
    const float* z   = (const float*)d_in[0];
    const float* emb = (const float*)d_in[1];
    if (n_in >= 2 && in_sizes[0] == NCODE * ZD && in_sizes[1] == NELEM) {
        const float* tmp = z; z = emb; emb = tmp;
    }
    float* out = (float*)d_out;

    cudaFuncSetAttribute(vq_argmin_3p,
                         cudaFuncAttributeMaxDynamicSharedMemorySize, SMEM_TOTAL);

    vq_embprep<<<NCODE, 256>>>(emb);
    vq_argmin_3p<<<NVEC / TILE_M, THREADS, SMEM_TOTAL>>>(z);
    vq_gather_kernel<<<ZB * (ZT / 32), 256>>>(z, emb, out);
    vq_finalize_kernel<<<1, 1024>>>(out, out_size);
}